// round 10
// baseline (speedup 1.0000x reference)
#include <cuda_runtime.h>
#include <math.h>

#define MAXN 50048
#define MAXE 1250048
#define F 64
#define D 256
#define SCAN_BS 1024
#define HB_BLOCKS 2048
#define SB_BLOCKS 2048

// Scratch (allocation-free __device__ globals)
__device__ float g_z[MAXN * F];
__device__ int   g_cnt[MAXN];
__device__ int   g_start[MAXN];
__device__ int   g_cursor[MAXN];
__device__ int   g_csr_src[MAXE];
__device__ int   g_bsum[256];
__device__ int   g_perm[MAXN];         // nodes partitioned by type
__device__ int   g_pcnt[2];

// ---- f32x2 packed-FMA helpers (Blackwell FFMA2 via PTX) ----
__device__ __forceinline__ unsigned long long pack2(float lo, float hi) {
    unsigned long long r;
    asm("mov.b64 %0, {%1, %2};" : "=l"(r) : "f"(lo), "f"(hi));
    return r;
}
__device__ __forceinline__ void fma2(unsigned long long& acc,
                                     unsigned long long a, unsigned long long b) {
    asm("fma.rn.f32x2 %0, %1, %2, %0;" : "+l"(acc) : "l"(a), "l"(b));
}
__device__ __forceinline__ float lo32(unsigned long long v) {
    return __uint_as_float((unsigned)(v & 0xffffffffull));
}
__device__ __forceinline__ float hi32(unsigned long long v) {
    return __uint_as_float((unsigned)(v >> 32));
}

// K0: zero counters
__global__ void k_init(int N) {
    int i = blockIdx.x * blockDim.x + threadIdx.x;
    if (i < N) g_cnt[i] = 0;
    if (i < 2) g_pcnt[i] = 0;
}

// K1: type partition perm (type1 front, type0 back)
__global__ void k_perm(const int* __restrict__ ntype, int N) {
    int i = blockIdx.x * blockDim.x + threadIdx.x;
    if (i < N) {
        if (ntype[i]) g_perm[atomicAdd(&g_pcnt[0], 1)] = i;
        else          g_perm[N - 1 - atomicAdd(&g_pcnt[1], 1)] = i;
    }
}

// Projection block body: 16 perm-slots starting at slot_base, 64 threads.
__device__ __forceinline__ void proj_block(const float* __restrict__ d_sim,
                                           const float* __restrict__ m_sim,
                                           const float* __restrict__ Wd,
                                           const float* __restrict__ Wm,
                                           const int* __restrict__ ntype,
                                           int N, int slot_base,
                                           float (*xs)[D], int* ids, int* ty) {
    int t = threadIdx.x;               // feature 0..63

    if (t < 16) {
        int slot = slot_base + t;
        int id = (slot < N) ? g_perm[slot] : g_perm[N - 1];
        ids[t] = id;
        ty[t] = ntype[id];
    }
    __syncthreads();

    for (int r = 0; r < 16; r++) {
        const float* p = ty[r] ? d_sim : m_sim;
        float4 v = ((const float4*)(p + (long)ids[r] * D))[t];
        ((float4*)xs[r])[t] = v;
    }
    __syncthreads();

    bool homo = true;
#pragma unroll
    for (int m = 1; m < 16; m++) homo &= (ty[m] == ty[0]);

    unsigned long long acc[16];
#pragma unroll
    for (int m = 0; m < 16; m++) acc[m] = 0ull;

    if (homo) {
        const float* wb = ty[0] ? Wd : Wm;
        for (int k = 0; k < D; k += 4) {
            float w0 = __ldg(wb + (k + 0) * F + t);
            float w1 = __ldg(wb + (k + 1) * F + t);
            float w2 = __ldg(wb + (k + 2) * F + t);
            float w3 = __ldg(wb + (k + 3) * F + t);
            unsigned long long w01 = pack2(w0, w1);
            unsigned long long w23 = pack2(w2, w3);
#pragma unroll
            for (int m = 0; m < 16; m++) {
                ulonglong2 x = *(const ulonglong2*)&xs[m][k];
                fma2(acc[m], x.x, w01);
                fma2(acc[m], x.y, w23);
            }
        }
    } else {
#pragma unroll 1
        for (int m = 0; m < 16; m++) {
            const float* wb = ty[m] ? Wd : Wm;
            for (int k = 0; k < D; k += 4) {
                unsigned long long w01 = pack2(__ldg(wb + (k + 0) * F + t),
                                               __ldg(wb + (k + 1) * F + t));
                unsigned long long w23 = pack2(__ldg(wb + (k + 2) * F + t),
                                               __ldg(wb + (k + 3) * F + t));
                ulonglong2 x = *(const ulonglong2*)&xs[m][k];
                fma2(acc[m], x.x, w01);
                fma2(acc[m], x.y, w23);
            }
        }
    }

#pragma unroll
    for (int m = 0; m < 16; m++) {
        int slot = slot_base + m;
        if (slot < N) g_z[(long)ids[m] * F + t] = lo32(acc[m]) + hi32(acc[m]);
    }
}

// M1: projection part A (blocks [0, PA)) ∥ dst histogram (blocks [PA, PA+HB))
__global__ void k_m1(const float* __restrict__ d_sim, const float* __restrict__ m_sim,
                     const float* __restrict__ Wd, const float* __restrict__ Wm,
                     const int* __restrict__ ntype, const int* __restrict__ dst,
                     int N, int E, int PA) {
    __shared__ float xs[16][D];
    __shared__ int ids[16];
    __shared__ int ty[16];
    int bid = blockIdx.x;
    if (bid < PA) {
        proj_block(d_sim, m_sim, Wd, Wm, ntype, N, bid * 16, xs, ids, ty);
    } else {
        int i = (bid - PA) * 64 + threadIdx.x;
        int stride = HB_BLOCKS * 64;
        for (; i < E; i += stride)
            atomicAdd(&g_cnt[dst[i]], 1);
    }
}

// M2: projection part B (blocks [0, PB)) ∥ CSR scatter (blocks [PB, PB+SB))
__global__ void k_m2(const float* __restrict__ d_sim, const float* __restrict__ m_sim,
                     const float* __restrict__ Wd, const float* __restrict__ Wm,
                     const int* __restrict__ ntype,
                     const int* __restrict__ src, const int* __restrict__ dst,
                     int N, int E, int NA, int PB) {
    __shared__ float xs[16][D];
    __shared__ int ids[16];
    __shared__ int ty[16];
    int bid = blockIdx.x;
    if (bid < PB) {
        proj_block(d_sim, m_sim, Wd, Wm, ntype, N, NA + bid * 16, xs, ids, ty);
    } else {
        int i = (bid - PB) * 64 + threadIdx.x;
        int stride = SB_BLOCKS * 64;
        for (; i < E; i += stride) {
            int pos = atomicAdd(&g_cursor[dst[i]], 1);
            g_csr_src[pos] = src[i];
        }
    }
}

// Scan: block-level exclusive scan (shfl), totals -> g_bsum
__global__ void k_scan_blocks(int N) {
    __shared__ int wsum[32];
    int t = threadIdx.x;
    int i = blockIdx.x * SCAN_BS + t;
    int v = (i < N) ? g_cnt[i] : 0;
    int x = v;
    int lane = t & 31, w = t >> 5;
#pragma unroll
    for (int o = 1; o < 32; o <<= 1) {
        int u = __shfl_up_sync(0xffffffffu, x, o);
        if (lane >= o) x += u;
    }
    if (lane == 31) wsum[w] = x;
    __syncthreads();
    if (w == 0) {
        int s = (lane < 32) ? wsum[lane] : 0;
#pragma unroll
        for (int o = 1; o < 32; o <<= 1) {
            int u = __shfl_up_sync(0xffffffffu, s, o);
            if (lane >= o) s += u;
        }
        wsum[lane] = s;
    }
    __syncthreads();
    int incl = x + (w > 0 ? wsum[w - 1] : 0);
    if (i < N) g_start[i] = incl - v;
    if (t == SCAN_BS - 1) g_bsum[blockIdx.x] = incl;
}

__global__ void k_scan_top(int NB) {
    __shared__ int ws[2];
    int t = threadIdx.x;                       // 64 threads
    int v0 = (t < NB) ? g_bsum[t] : 0;
    int v = v0;
    int lane = t & 31, w = t >> 5;
#pragma unroll
    for (int o = 1; o < 32; o <<= 1) {
        int u = __shfl_up_sync(0xffffffffu, v, o);
        if (lane >= o) v += u;
    }
    if (lane == 31) ws[w] = v;
    __syncthreads();
    if (w == 1) v += ws[0];
    if (t < NB) g_bsum[t] = v - v0;
}

__global__ void k_add_off(int N) {
    int i = blockIdx.x * blockDim.x + threadIdx.x;
    if (i < N) {
        int s = g_start[i] + g_bsum[i / SCAN_BS];
        g_start[i] = s;
        g_cursor[i] = s;
    }
}

// Fused online-softmax aggregation + ELU.
// ONE WARP per dst node; 2 edges per iteration (lanes 0-15 edge e, 16-31 edge e+1).
// Both halves keep duplicate h/s over the same 64 features; shared max trajectory.
__global__ void k_fused(float* __restrict__ out, int N, int E) {
    int wid = blockIdx.x * (blockDim.x >> 5) + (threadIdx.x >> 5);
    int lane = threadIdx.x & 31;
    int half = lane >> 4;          // 0 or 1
    int hl = lane & 15;            // lane within half
    const unsigned FULL = 0xffffffffu;
    if (wid >= N) return;
    int d = wid;

    int beg = g_start[d];
    int end = (d + 1 < N) ? g_start[d + 1] : E;

    if (beg == end) {
        if (half == 0)
            ((float4*)(out + (long)d * F))[hl] = make_float4(0.f, 0.f, 0.f, 0.f);
        return;
    }

    float4 zd = __ldg(((const float4*)(g_z + (long)d * F)) + hl);

    float m = -INFINITY, s = 0.0f;
    float4 h = make_float4(0.f, 0.f, 0.f, 0.f);

    // Pipeline: my edge slots are beg+half, beg+half+2, ...
    int my0 = beg + half;
    int i0 = (my0 < end) ? __ldg(g_csr_src + my0) : 0;
    float4 zs = __ldg(((const float4*)(g_z + (long)i0 * F)) + hl);
    int i1 = (my0 + 2 < end) ? __ldg(g_csr_src + my0 + 2) : 0;

    for (int e0 = beg; e0 < end; e0 += 2) {
        float4 cur = zs;
        bool curv = (e0 + half) < end;
        if (e0 + 2 < end)
            zs = __ldg(((const float4*)(g_z + (long)i1 * F)) + hl);
        if (e0 + 4 + half < end)
            i1 = __ldg(g_csr_src + e0 + 4 + half);

        float p = cur.x * zd.x + cur.y * zd.y + cur.z * zd.z + cur.w * zd.w;
        p += __shfl_xor_sync(FULL, p, 1);
        p += __shfl_xor_sync(FULL, p, 2);
        p += __shfl_xor_sync(FULL, p, 4);
        p += __shfl_xor_sync(FULL, p, 8);
        float ea = curv ? (p > 0.0f ? p : 0.2f * p) : -INFINITY;  // leaky_relu
        float eao = __shfl_xor_sync(FULL, ea, 16);
        float mn = fmaxf(m, fmaxf(ea, eao));      // warp-uniform

        if (mn <= m) {                            // no new max (uniform branch)
            float w = __expf(ea - m);             // 0 for invalid edge
            s += w;
            h.x = fmaf(w, cur.x, h.x);
            h.y = fmaf(w, cur.y, h.y);
            h.z = fmaf(w, cur.z, h.z);
            h.w = fmaf(w, cur.w, h.w);
        } else {
            float c = __expf(m - mn);             // first iter: exp(-inf)=0
            float w = __expf(ea - mn);
            s = fmaf(s, c, w);
            h.x = fmaf(h.x, c, w * cur.x);
            h.y = fmaf(h.y, c, w * cur.y);
            h.z = fmaf(h.z, c, w * cur.z);
            h.w = fmaf(h.w, c, w * cur.w);
            m = mn;
        }
    }

    // Combine the two halves (same m trajectory -> direct add)
    s   += __shfl_xor_sync(FULL, s, 16);
    h.x += __shfl_xor_sync(FULL, h.x, 16);
    h.y += __shfl_xor_sync(FULL, h.y, 16);
    h.z += __shfl_xor_sync(FULL, h.z, 16);
    h.w += __shfl_xor_sync(FULL, h.w, 16);

    if (half == 0) {
        float inv = 1.0f / s;                     // s >= 1 (max term present)
        float4 o;
        float x;
        x = h.x * inv; o.x = x > 0.0f ? x : expm1f(x);
        x = h.y * inv; o.y = x > 0.0f ? x : expm1f(x);
        x = h.z * inv; o.z = x > 0.0f ? x : expm1f(x);
        x = h.w * inv; o.w = x > 0.0f ? x : expm1f(x);
        ((float4*)(out + (long)d * F))[hl] = o;
    }
}

extern "C" void kernel_launch(void* const* d_in, const int* in_sizes, int n_in,
                              void* d_out, int out_size) {
    const float* d_sim = (const float*)d_in[0];
    const float* m_sim = (const float*)d_in[1];
    const float* Wd    = (const float*)d_in[2];
    const float* Wm    = (const float*)d_in[3];
    const int*   ntype = (const int*)d_in[4];
    const int*   src   = (const int*)d_in[5];
    const int*   dst   = (const int*)d_in[6];
    float* out = (float*)d_out;

    int N = in_sizes[4];
    int E = in_sizes[5];
    int NB = (N + SCAN_BS - 1) / SCAN_BS;

    int NA = ((N / 2) / 16) * 16;                 // proj split point (multiple of 16)
    int PA = (NA + 15) / 16;                      // proj blocks in M1
    int PB = (N - NA + 15) / 16;                  // proj blocks in M2

    k_init<<<(N + 255) / 256, 256>>>(N);
    k_perm<<<(N + 255) / 256, 256>>>(ntype, N);
    k_m1<<<PA + HB_BLOCKS, 64>>>(d_sim, m_sim, Wd, Wm, ntype, dst, N, E, PA);
    k_scan_blocks<<<NB, SCAN_BS>>>(N);
    k_scan_top<<<1, 64>>>(NB);
    k_add_off<<<(N + 255) / 256, 256>>>(N);
    k_m2<<<PB + SB_BLOCKS, 64>>>(d_sim, m_sim, Wd, Wm, ntype, src, dst, N, E, NA, PB);
    {
        int warps_per_block = 256 / 32;
        int blocks = (N + warps_per_block - 1) / warps_per_block;
        k_fused<<<blocks, 256>>>(out, N, E);
    }
}

// round 14
// speedup vs baseline: 1.0678x; 1.0678x over previous
#include <cuda_runtime.h>
#include <math.h>

#define MAXN 50048
#define MAXE 1250048
#define F 64
#define D 256
#define SCAN_BS 1024
#define SB_BLOCKS 2048

// Scratch (allocation-free __device__ globals; zero-initialized at load)
__device__ float g_z[MAXN * F];
__device__ int   g_cnt[MAXN];          // degree counts (re-zeroed each call by k_addoff)
__device__ int   g_start[MAXN];
__device__ int   g_cursor[MAXN];
__device__ int   g_csr_src[MAXE];
__device__ int   g_bsum[64];
__device__ int   g_perm[MAXN];
__device__ int   g_pcnt[2];            // re-zeroed each call by k_m2

// ---- f32x2 packed-FMA helpers (Blackwell FFMA2 via PTX) ----
__device__ __forceinline__ unsigned long long pack2(float lo, float hi) {
    unsigned long long r;
    asm("mov.b64 %0, {%1, %2};" : "=l"(r) : "f"(lo), "f"(hi));
    return r;
}
__device__ __forceinline__ void fma2(unsigned long long& acc,
                                     unsigned long long a, unsigned long long b) {
    asm("fma.rn.f32x2 %0, %1, %2, %0;" : "+l"(acc) : "l"(a), "l"(b));
}
__device__ __forceinline__ float lo32(unsigned long long v) {
    return __uint_as_float((unsigned)(v & 0xffffffffull));
}
__device__ __forceinline__ float hi32(unsigned long long v) {
    return __uint_as_float((unsigned)(v >> 32));
}

// L1: dst histogram (i<E) + type partition perm (i<N)
__global__ void k_pre(const int* __restrict__ ntype, const int* __restrict__ dst,
                      int N, int E) {
    int i = blockIdx.x * blockDim.x + threadIdx.x;
    if (i < E) atomicAdd(&g_cnt[dst[i]], 1);
    if (i < N) {
        if (ntype[i]) g_perm[atomicAdd(&g_pcnt[0], 1)] = i;
        else          g_perm[N - 1 - atomicAdd(&g_pcnt[1], 1)] = i;
    }
}

// L2: block-level exclusive scan (shfl), totals -> g_bsum
__global__ void k_scan_blocks(int N) {
    __shared__ int wsum[32];
    int t = threadIdx.x;
    int i = blockIdx.x * SCAN_BS + t;
    int v = (i < N) ? g_cnt[i] : 0;
    int x = v;
    int lane = t & 31, w = t >> 5;
#pragma unroll
    for (int o = 1; o < 32; o <<= 1) {
        int u = __shfl_up_sync(0xffffffffu, x, o);
        if (lane >= o) x += u;
    }
    if (lane == 31) wsum[w] = x;
    __syncthreads();
    if (w == 0) {
        int s = (lane < 32) ? wsum[lane] : 0;
#pragma unroll
        for (int o = 1; o < 32; o <<= 1) {
            int u = __shfl_up_sync(0xffffffffu, s, o);
            if (lane >= o) s += u;
        }
        wsum[lane] = s;
    }
    __syncthreads();
    int incl = x + (w > 0 ? wsum[w - 1] : 0);
    if (i < N) g_start[i] = incl - v;
    if (t == SCAN_BS - 1) g_bsum[blockIdx.x] = incl;
}

// L3: add block offsets (top-level scan recomputed redundantly per block — no
// inter-block communication), init cursors, re-zero g_cnt for next replay.
__global__ void k_addoff(int N, int NB) {
    __shared__ int sh[64];
    int t = threadIdx.x;               // 256 threads
    if (t < 64) sh[t] = (t < NB) ? g_bsum[t] : 0;
    __syncthreads();
#pragma unroll
    for (int o = 1; o < 64; o <<= 1) {
        int add = (t >= o && t < 64) ? sh[t - o] : 0;
        __syncthreads();
        if (t < 64) sh[t] += add;
        __syncthreads();
    }
    int i = blockIdx.x * blockDim.x + t;
    if (i < N) {
        int blk = i / SCAN_BS;
        int s = g_start[i] + (blk > 0 ? sh[blk - 1] : 0);
        g_start[i]  = s;
        g_cursor[i] = s;
        g_cnt[i]    = 0;               // reset for next call
    }
}

// Projection block body: 16 perm-slots starting at slot_base, 64 threads.
__device__ __forceinline__ void proj_block(const float* __restrict__ d_sim,
                                           const float* __restrict__ m_sim,
                                           const float* __restrict__ Wd,
                                           const float* __restrict__ Wm,
                                           const int* __restrict__ ntype,
                                           int N, int slot_base,
                                           float (*xs)[D], int* ids, int* ty) {
    int t = threadIdx.x;               // feature 0..63

    if (t < 16) {
        int slot = slot_base + t;
        int id = (slot < N) ? g_perm[slot] : g_perm[N - 1];
        ids[t] = id;
        ty[t] = ntype[id];
    }
    __syncthreads();

    for (int r = 0; r < 16; r++) {
        const float* p = ty[r] ? d_sim : m_sim;
        float4 v = ((const float4*)(p + (long)ids[r] * D))[t];
        ((float4*)xs[r])[t] = v;
    }
    __syncthreads();

    bool homo = true;
#pragma unroll
    for (int m = 1; m < 16; m++) homo &= (ty[m] == ty[0]);

    unsigned long long acc[16];
#pragma unroll
    for (int m = 0; m < 16; m++) acc[m] = 0ull;

    if (homo) {
        const float* wb = ty[0] ? Wd : Wm;
        for (int k = 0; k < D; k += 4) {
            float w0 = __ldg(wb + (k + 0) * F + t);
            float w1 = __ldg(wb + (k + 1) * F + t);
            float w2 = __ldg(wb + (k + 2) * F + t);
            float w3 = __ldg(wb + (k + 3) * F + t);
            unsigned long long w01 = pack2(w0, w1);
            unsigned long long w23 = pack2(w2, w3);
#pragma unroll
            for (int m = 0; m < 16; m++) {
                ulonglong2 x = *(const ulonglong2*)&xs[m][k];
                fma2(acc[m], x.x, w01);
                fma2(acc[m], x.y, w23);
            }
        }
    } else {
#pragma unroll 1
        for (int m = 0; m < 16; m++) {
            const float* wb = ty[m] ? Wd : Wm;
            for (int k = 0; k < D; k += 4) {
                unsigned long long w01 = pack2(__ldg(wb + (k + 0) * F + t),
                                               __ldg(wb + (k + 1) * F + t));
                unsigned long long w23 = pack2(__ldg(wb + (k + 2) * F + t),
                                               __ldg(wb + (k + 3) * F + t));
                ulonglong2 x = *(const ulonglong2*)&xs[m][k];
                fma2(acc[m], x.x, w01);
                fma2(acc[m], x.y, w23);
            }
        }
    }

#pragma unroll
    for (int m = 0; m < 16; m++) {
        int slot = slot_base + m;
        if (slot < N) g_z[(long)ids[m] * F + t] = lo32(acc[m]) + hi32(acc[m]);
    }
}

// L4: projection (blocks [0, PB)) ∥ CSR scatter (blocks [PB, PB+SB_BLOCKS)) + cleanup
__global__ void k_m2(const float* __restrict__ d_sim, const float* __restrict__ m_sim,
                     const float* __restrict__ Wd, const float* __restrict__ Wm,
                     const int* __restrict__ ntype,
                     const int* __restrict__ src, const int* __restrict__ dst,
                     int N, int E, int PB) {
    __shared__ float xs[16][D];
    __shared__ int ids[16];
    __shared__ int ty[16];
    int bid = blockIdx.x;
    if (bid < PB) {
        proj_block(d_sim, m_sim, Wd, Wm, ntype, N, bid * 16, xs, ids, ty);
    } else {
        int i = (bid - PB) * 64 + threadIdx.x;
        if (i < 2) g_pcnt[i] = 0;      // reset for next call
        int stride = SB_BLOCKS * 64;
        for (; i < E; i += stride) {
            int pos = atomicAdd(&g_cursor[dst[i]], 1);
            g_csr_src[pos] = src[i];
        }
    }
}

// L5: fused online-softmax aggregation + ELU (half-warp per dst node).
// 2-deep prefetch; __ldcg row gathers (L2-only — z is 12.8MB, keep L1 for idx).
__global__ void k_fused(float* __restrict__ out, int N, int E) {
    int hw = blockIdx.x * (blockDim.x >> 4) + (threadIdx.x >> 4);
    int lane = threadIdx.x & 15;
    unsigned mask = 0xFFFFu << (threadIdx.x & 0x10);
    if (hw >= N) return;
    int d = hw;

    int beg = g_start[d];
    int end = (d + 1 < N) ? g_start[d + 1] : E;

    if (beg == end) {
        ((float4*)(out + (long)d * F))[lane] = make_float4(0.f, 0.f, 0.f, 0.f);
        return;
    }

    float4 zd = __ldg(((const float4*)(g_z + (long)d * F)) + lane);

    float m = -INFINITY, s = 0.0f;
    float4 h = make_float4(0.f, 0.f, 0.f, 0.f);

    // 2-deep pipeline: idx 2-ahead, row 1-ahead
    int i0 = __ldg(g_csr_src + beg);
    float4 zs = __ldcg(((const float4*)(g_z + (long)i0 * F)) + lane);
    int i1 = (beg + 1 < end) ? __ldg(g_csr_src + beg + 1) : 0;

    for (int e = beg; e < end; e++) {
        float4 cur = zs;
        if (e + 1 < end)
            zs = __ldcg(((const float4*)(g_z + (long)i1 * F)) + lane);
        if (e + 2 < end)
            i1 = __ldg(g_csr_src + e + 2);

        float p = cur.x * zd.x + cur.y * zd.y + cur.z * zd.z + cur.w * zd.w;
        p += __shfl_xor_sync(mask, p, 1);
        p += __shfl_xor_sync(mask, p, 2);
        p += __shfl_xor_sync(mask, p, 4);
        p += __shfl_xor_sync(mask, p, 8);
        float ea = p > 0.0f ? p : 0.2f * p;          // leaky_relu
        if (ea <= m) {
            float w = __expf(ea - m);
            s += w;
            h.x = fmaf(w, cur.x, h.x);
            h.y = fmaf(w, cur.y, h.y);
            h.z = fmaf(w, cur.z, h.z);
            h.w = fmaf(w, cur.w, h.w);
        } else {
            float c = __expf(m - ea);                // first iter: exp(-inf)=0
            s = fmaf(s, c, 1.0f);
            h.x = fmaf(h.x, c, cur.x);
            h.y = fmaf(h.y, c, cur.y);
            h.z = fmaf(h.z, c, cur.z);
            h.w = fmaf(h.w, c, cur.w);
            m = ea;
        }
    }

    float inv = 1.0f / s;                            // s >= 1 (max term)
    float4 o;
    float x;
    x = h.x * inv; o.x = x > 0.0f ? x : expm1f(x);
    x = h.y * inv; o.y = x > 0.0f ? x : expm1f(x);
    x = h.z * inv; o.z = x > 0.0f ? x : expm1f(x);
    x = h.w * inv; o.w = x > 0.0f ? x : expm1f(x);
    ((float4*)(out + (long)d * F))[lane] = o;
}

extern "C" void kernel_launch(void* const* d_in, const int* in_sizes, int n_in,
                              void* d_out, int out_size) {
    const float* d_sim = (const float*)d_in[0];
    const float* m_sim = (const float*)d_in[1];
    const float* Wd    = (const float*)d_in[2];
    const float* Wm    = (const float*)d_in[3];
    const int*   ntype = (const int*)d_in[4];
    const int*   src   = (const int*)d_in[5];
    const int*   dst   = (const int*)d_in[6];
    float* out = (float*)d_out;

    int N = in_sizes[4];
    int E = in_sizes[5];
    int NB = (N + SCAN_BS - 1) / SCAN_BS;
    int PB = (N + 15) / 16;

    k_pre<<<(max(N, E) + 255) / 256, 256>>>(ntype, dst, N, E);
    k_scan_blocks<<<NB, SCAN_BS>>>(N);
    k_addoff<<<(N + 255) / 256, 256>>>(N, NB);
    k_m2<<<PB + SB_BLOCKS, 64>>>(d_sim, m_sim, Wd, Wm, ntype, src, dst, N, E, PB);
    {
        int hw_per_block = 256 / 16;
        int blocks = (N + hw_per_block - 1) / hw_per_block;
        k_fused<<<blocks, 256>>>(out, N, E);
    }
}

// round 15
// speedup vs baseline: 1.0991x; 1.0293x over previous
#include <cuda_runtime.h>
#include <math.h>

#define MAXN 50048
#define MAXE 1250048
#define F 64
#define D 256
#define SCAN_BS 1024
#define SB_BLOCKS 1024

// Scratch (allocation-free __device__ globals; zero-initialized at load)
__device__ float g_z[MAXN * F];
__device__ int   g_cnt[MAXN];          // degree counts (re-zeroed each call by k_addoff)
__device__ int   g_start[MAXN];
__device__ int   g_cursor[MAXN];
__device__ int   g_csr_src[MAXE];
__device__ int   g_bsum[64];
__device__ int   g_perm[MAXN];
__device__ int   g_pcnt[2];            // re-zeroed each call by k_m2

// ---- f32x2 packed-FMA helpers (Blackwell FFMA2 via PTX) ----
__device__ __forceinline__ unsigned long long pack2(float lo, float hi) {
    unsigned long long r;
    asm("mov.b64 %0, {%1, %2};" : "=l"(r) : "f"(lo), "f"(hi));
    return r;
}
__device__ __forceinline__ void fma2(unsigned long long& acc,
                                     unsigned long long a, unsigned long long b) {
    asm("fma.rn.f32x2 %0, %1, %2, %0;" : "+l"(acc) : "l"(a), "l"(b));
}
__device__ __forceinline__ float lo32(unsigned long long v) {
    return __uint_as_float((unsigned)(v & 0xffffffffull));
}
__device__ __forceinline__ float hi32(unsigned long long v) {
    return __uint_as_float((unsigned)(v >> 32));
}

// L1: dst histogram (i<E) + type partition perm (i<N)
__global__ void k_pre(const int* __restrict__ ntype, const int* __restrict__ dst,
                      int N, int E) {
    int i = blockIdx.x * blockDim.x + threadIdx.x;
    if (i < E) atomicAdd(&g_cnt[dst[i]], 1);
    if (i < N) {
        if (ntype[i]) g_perm[atomicAdd(&g_pcnt[0], 1)] = i;
        else          g_perm[N - 1 - atomicAdd(&g_pcnt[1], 1)] = i;
    }
}

// L2: block-level exclusive scan (shfl), totals -> g_bsum
__global__ void k_scan_blocks(int N) {
    __shared__ int wsum[32];
    int t = threadIdx.x;
    int i = blockIdx.x * SCAN_BS + t;
    int v = (i < N) ? g_cnt[i] : 0;
    int x = v;
    int lane = t & 31, w = t >> 5;
#pragma unroll
    for (int o = 1; o < 32; o <<= 1) {
        int u = __shfl_up_sync(0xffffffffu, x, o);
        if (lane >= o) x += u;
    }
    if (lane == 31) wsum[w] = x;
    __syncthreads();
    if (w == 0) {
        int s = (lane < 32) ? wsum[lane] : 0;
#pragma unroll
        for (int o = 1; o < 32; o <<= 1) {
            int u = __shfl_up_sync(0xffffffffu, s, o);
            if (lane >= o) s += u;
        }
        wsum[lane] = s;
    }
    __syncthreads();
    int incl = x + (w > 0 ? wsum[w - 1] : 0);
    if (i < N) g_start[i] = incl - v;
    if (t == SCAN_BS - 1) g_bsum[blockIdx.x] = incl;
}

// L3: add block offsets (top scan recomputed redundantly per block), init cursors,
// re-zero g_cnt for next replay.
__global__ void k_addoff(int N, int NB) {
    __shared__ int sh[64];
    int t = threadIdx.x;               // 256 threads
    if (t < 64) sh[t] = (t < NB) ? g_bsum[t] : 0;
    __syncthreads();
#pragma unroll
    for (int o = 1; o < 64; o <<= 1) {
        int add = (t >= o && t < 64) ? sh[t - o] : 0;
        __syncthreads();
        if (t < 64) sh[t] += add;
        __syncthreads();
    }
    int i = blockIdx.x * blockDim.x + t;
    if (i < N) {
        int blk = i / SCAN_BS;
        int s = g_start[i] + (blk > 0 ? sh[blk - 1] : 0);
        g_start[i]  = s;
        g_cursor[i] = s;
        g_cnt[i]    = 0;               // reset for next call
    }
}

// L4: projection (blocks [0, PB)) ∥ CSR scatter (blocks [PB, PB+SB_BLOCKS)) + cleanup.
// Projection: 16 nodes per block, 128 threads = 2 groups × 64 features.
// Group g handles nodes 8g..8g+7 -> acc[8] (16 regs), 52 warps/SM occupancy.
__global__ void __launch_bounds__(128)
k_m2(const float* __restrict__ d_sim, const float* __restrict__ m_sim,
     const float* __restrict__ Wd, const float* __restrict__ Wm,
     const int* __restrict__ ntype,
     const int* __restrict__ src, const int* __restrict__ dst,
     int N, int E, int PB) {
    __shared__ float xs[16][D];
    __shared__ int ids[16];
    __shared__ int ty[16];
    int bid = blockIdx.x;

    if (bid < PB) {
        int t = threadIdx.x;           // 0..127
        int feat = t & 63;
        int nb = (t >> 6) * 8;         // node base for my group: 0 or 8
        int slot_base = bid * 16;

        if (t < 16) {
            int slot = slot_base + t;
            int id = (slot < N) ? g_perm[slot] : g_perm[N - 1];
            ids[t] = id;
            ty[t] = ntype[id];
        }
        __syncthreads();

        // Stage 16 rows: 1024 float4 slots across 128 threads (8 each), coalesced.
        for (int i = t; i < 16 * (D / 4); i += 128) {
            int r = i >> 6;            // D/4 == 64
            int c = i & 63;
            const float* p = ty[r] ? d_sim : m_sim;
            ((float4*)xs[r])[c] = ((const float4*)(p + (long)ids[r] * D))[c];
        }
        __syncthreads();

        bool homo = true;
#pragma unroll
        for (int m = 1; m < 16; m++) homo &= (ty[m] == ty[0]);

        unsigned long long acc[8];
#pragma unroll
        for (int m = 0; m < 8; m++) acc[m] = 0ull;

        if (homo) {
            const float* wb = ty[0] ? Wd : Wm;
#pragma unroll 2
            for (int k = 0; k < D; k += 4) {
                float w0 = __ldg(wb + (k + 0) * F + feat);
                float w1 = __ldg(wb + (k + 1) * F + feat);
                float w2 = __ldg(wb + (k + 2) * F + feat);
                float w3 = __ldg(wb + (k + 3) * F + feat);
                unsigned long long w01 = pack2(w0, w1);
                unsigned long long w23 = pack2(w2, w3);
#pragma unroll
                for (int m = 0; m < 8; m++) {
                    ulonglong2 x = *(const ulonglong2*)&xs[nb + m][k];
                    fma2(acc[m], x.x, w01);
                    fma2(acc[m], x.y, w23);
                }
            }
        } else {
            // Rare boundary block: per-node W, same even/odd summation order.
#pragma unroll 1
            for (int m = 0; m < 8; m++) {
                const float* wb = ty[nb + m] ? Wd : Wm;
                for (int k = 0; k < D; k += 4) {
                    unsigned long long w01 = pack2(__ldg(wb + (k + 0) * F + feat),
                                                   __ldg(wb + (k + 1) * F + feat));
                    unsigned long long w23 = pack2(__ldg(wb + (k + 2) * F + feat),
                                                   __ldg(wb + (k + 3) * F + feat));
                    ulonglong2 x = *(const ulonglong2*)&xs[nb + m][k];
                    fma2(acc[m], x.x, w01);
                    fma2(acc[m], x.y, w23);
                }
            }
        }

#pragma unroll
        for (int m = 0; m < 8; m++) {
            int slot = slot_base + nb + m;
            if (slot < N) g_z[(long)ids[nb + m] * F + feat] = lo32(acc[m]) + hi32(acc[m]);
        }
    } else {
        int i = (bid - PB) * 128 + threadIdx.x;
        if (i < 2) g_pcnt[i] = 0;      // reset for next call
        int stride = SB_BLOCKS * 128;
        for (; i < E; i += stride) {
            int pos = atomicAdd(&g_cursor[dst[i]], 1);
            g_csr_src[pos] = src[i];
        }
    }
}

// L5: fused online-softmax aggregation + ELU (half-warp per dst node).
// 2-deep prefetch; __ldcg row gathers (L2-only — z is 12.8MB, keep L1 for idx).
__global__ void k_fused(float* __restrict__ out, int N, int E) {
    int hw = blockIdx.x * (blockDim.x >> 4) + (threadIdx.x >> 4);
    int lane = threadIdx.x & 15;
    unsigned mask = 0xFFFFu << (threadIdx.x & 0x10);
    if (hw >= N) return;
    int d = hw;

    int beg = g_start[d];
    int end = (d + 1 < N) ? g_start[d + 1] : E;

    if (beg == end) {
        ((float4*)(out + (long)d * F))[lane] = make_float4(0.f, 0.f, 0.f, 0.f);
        return;
    }

    float4 zd = __ldg(((const float4*)(g_z + (long)d * F)) + lane);

    float m = -INFINITY, s = 0.0f;
    float4 h = make_float4(0.f, 0.f, 0.f, 0.f);

    // 2-deep pipeline: idx 2-ahead, row 1-ahead
    int i0 = __ldg(g_csr_src + beg);
    float4 zs = __ldcg(((const float4*)(g_z + (long)i0 * F)) + lane);
    int i1 = (beg + 1 < end) ? __ldg(g_csr_src + beg + 1) : 0;

    for (int e = beg; e < end; e++) {
        float4 cur = zs;
        if (e + 1 < end)
            zs = __ldcg(((const float4*)(g_z + (long)i1 * F)) + lane);
        if (e + 2 < end)
            i1 = __ldg(g_csr_src + e + 2);

        float p = cur.x * zd.x + cur.y * zd.y + cur.z * zd.z + cur.w * zd.w;
        p += __shfl_xor_sync(mask, p, 1);
        p += __shfl_xor_sync(mask, p, 2);
        p += __shfl_xor_sync(mask, p, 4);
        p += __shfl_xor_sync(mask, p, 8);
        float ea = p > 0.0f ? p : 0.2f * p;          // leaky_relu
        if (ea <= m) {
            float w = __expf(ea - m);
            s += w;
            h.x = fmaf(w, cur.x, h.x);
            h.y = fmaf(w, cur.y, h.y);
            h.z = fmaf(w, cur.z, h.z);
            h.w = fmaf(w, cur.w, h.w);
        } else {
            float c = __expf(m - ea);                // first iter: exp(-inf)=0
            s = fmaf(s, c, 1.0f);
            h.x = fmaf(h.x, c, cur.x);
            h.y = fmaf(h.y, c, cur.y);
            h.z = fmaf(h.z, c, cur.z);
            h.w = fmaf(h.w, c, cur.w);
            m = ea;
        }
    }

    float inv = 1.0f / s;                            // s >= 1 (max term)
    float4 o;
    float x;
    x = h.x * inv; o.x = x > 0.0f ? x : expm1f(x);
    x = h.y * inv; o.y = x > 0.0f ? x : expm1f(x);
    x = h.z * inv; o.z = x > 0.0f ? x : expm1f(x);
    x = h.w * inv; o.w = x > 0.0f ? x : expm1f(x);
    ((float4*)(out + (long)d * F))[lane] = o;
}

extern "C" void kernel_launch(void* const* d_in, const int* in_sizes, int n_in,
                              void* d_out, int out_size) {
    const float* d_sim = (const float*)d_in[0];
    const float* m_sim = (const float*)d_in[1];
    const float* Wd    = (const float*)d_in[2];
    const float* Wm    = (const float*)d_in[3];
    const int*   ntype = (const int*)d_in[4];
    const int*   src   = (const int*)d_in[5];
    const int*   dst   = (const int*)d_in[6];
    float* out = (float*)d_out;

    int N = in_sizes[4];
    int E = in_sizes[5];
    int NB = (N + SCAN_BS - 1) / SCAN_BS;
    int PB = (N + 15) / 16;

    k_pre<<<(max(N, E) + 255) / 256, 256>>>(ntype, dst, N, E);
    k_scan_blocks<<<NB, SCAN_BS>>>(N);
    k_addoff<<<(N + 255) / 256, 256>>>(N, NB);
    k_m2<<<PB + SB_BLOCKS, 128>>>(d_sim, m_sim, Wd, Wm, ntype, src, dst, N, E, PB);
    {
        int hw_per_block = 256 / 16;
        int blocks = (N + hw_per_block - 1) / hw_per_block;
        k_fused<<<blocks, 256>>>(out, N, E);
    }
}

// round 17
// speedup vs baseline: 1.1205x; 1.0195x over previous
#include <cuda_runtime.h>
#include <math.h>

#define MAXN 50048
#define MAXE 1250048
#define F 64
#define D 256
#define SCAN_BS 1024
#define SB_BLOCKS 1024

// Scratch (allocation-free __device__ globals; zero-initialized at load)
__device__ float g_z[MAXN * F];
__device__ int   g_cnt[MAXN];          // degree counts (re-zeroed each call by k_addoff)
__device__ int   g_start[MAXN];
__device__ int   g_cursor[MAXN];
__device__ int   g_csr_src[MAXE];
__device__ int   g_bsum[64];
__device__ int   g_perm[MAXN];
__device__ int   g_pcnt[2];            // re-zeroed each call by k_m2

// ---- f32x2 packed-FMA helpers (Blackwell FFMA2 via PTX) ----
__device__ __forceinline__ unsigned long long pack2(float lo, float hi) {
    unsigned long long r;
    asm("mov.b64 %0, {%1, %2};" : "=l"(r) : "f"(lo), "f"(hi));
    return r;
}
__device__ __forceinline__ void fma2(unsigned long long& acc,
                                     unsigned long long a, unsigned long long b) {
    asm("fma.rn.f32x2 %0, %1, %2, %0;" : "+l"(acc) : "l"(a), "l"(b));
}
__device__ __forceinline__ float lo32(unsigned long long v) {
    return __uint_as_float((unsigned)(v & 0xffffffffull));
}
__device__ __forceinline__ float hi32(unsigned long long v) {
    return __uint_as_float((unsigned)(v >> 32));
}

// L1: dst histogram (i<E) + type partition perm (i<N)
__global__ void k_pre(const int* __restrict__ ntype, const int* __restrict__ dst,
                      int N, int E) {
    int i = blockIdx.x * blockDim.x + threadIdx.x;
    if (i < E) atomicAdd(&g_cnt[dst[i]], 1);
    if (i < N) {
        if (ntype[i]) g_perm[atomicAdd(&g_pcnt[0], 1)] = i;
        else          g_perm[N - 1 - atomicAdd(&g_pcnt[1], 1)] = i;
    }
}

// L2: block-level exclusive scan (shfl), totals -> g_bsum
__global__ void k_scan_blocks(int N) {
    __shared__ int wsum[32];
    int t = threadIdx.x;
    int i = blockIdx.x * SCAN_BS + t;
    int v = (i < N) ? g_cnt[i] : 0;
    int x = v;
    int lane = t & 31, w = t >> 5;
#pragma unroll
    for (int o = 1; o < 32; o <<= 1) {
        int u = __shfl_up_sync(0xffffffffu, x, o);
        if (lane >= o) x += u;
    }
    if (lane == 31) wsum[w] = x;
    __syncthreads();
    if (w == 0) {
        int s = (lane < 32) ? wsum[lane] : 0;
#pragma unroll
        for (int o = 1; o < 32; o <<= 1) {
            int u = __shfl_up_sync(0xffffffffu, s, o);
            if (lane >= o) s += u;
        }
        wsum[lane] = s;
    }
    __syncthreads();
    int incl = x + (w > 0 ? wsum[w - 1] : 0);
    if (i < N) g_start[i] = incl - v;
    if (t == SCAN_BS - 1) g_bsum[blockIdx.x] = incl;
}

// L3: add block offsets (top scan recomputed redundantly per block), init cursors,
// re-zero g_cnt for next replay.
__global__ void k_addoff(int N, int NB) {
    __shared__ int sh[64];
    int t = threadIdx.x;               // 256 threads
    if (t < 64) sh[t] = (t < NB) ? g_bsum[t] : 0;
    __syncthreads();
#pragma unroll
    for (int o = 1; o < 64; o <<= 1) {
        int add = (t >= o && t < 64) ? sh[t - o] : 0;
        __syncthreads();
        if (t < 64) sh[t] += add;
        __syncthreads();
    }
    int i = blockIdx.x * blockDim.x + t;
    if (i < N) {
        int blk = i / SCAN_BS;
        int s = g_start[i] + (blk > 0 ? sh[blk - 1] : 0);
        g_start[i]  = s;
        g_cursor[i] = s;
        g_cnt[i]    = 0;               // reset for next call
    }
}

// L4: projection (blocks [0, PB)) ∥ CSR scatter (blocks [PB, PB+SB_BLOCKS)) + cleanup.
// Projection: 16 nodes/block, 128 threads = 2 groups × 64 features, 8 nodes/group.
// Inner k-loop: chunks of 8, PING-PONG register double-buffering — chunk B's
// LDS/LDG issue before chunk A's FFMA2s, hiding the 29-cyc LDS latency.
__global__ void __launch_bounds__(128)
k_m2(const float* __restrict__ d_sim, const float* __restrict__ m_sim,
     const float* __restrict__ Wd, const float* __restrict__ Wm,
     const int* __restrict__ ntype,
     const int* __restrict__ src, const int* __restrict__ dst,
     int N, int E, int PB) {
    __shared__ float xs[16][D];
    __shared__ int ids[16];
    __shared__ int ty[16];
    int bid = blockIdx.x;

    if (bid < PB) {
        int t = threadIdx.x;           // 0..127
        int feat = t & 63;
        int nb = (t >> 6) * 8;         // node base for my group: 0 or 8
        int slot_base = bid * 16;

        if (t < 16) {
            int slot = slot_base + t;
            int id = (slot < N) ? g_perm[slot] : g_perm[N - 1];
            ids[t] = id;
            ty[t] = ntype[id];
        }
        __syncthreads();

        // Stage 16 rows: 1024 float4 slots across 128 threads, coalesced.
        for (int i = t; i < 16 * (D / 4); i += 128) {
            int r = i >> 6;            // D/4 == 64
            int c = i & 63;
            const float* p = ty[r] ? d_sim : m_sim;
            ((float4*)xs[r])[c] = ((const float4*)(p + (long)ids[r] * D))[c];
        }
        __syncthreads();

        bool homo = true;
#pragma unroll
        for (int m = 1; m < 16; m++) homo &= (ty[m] == ty[0]);

        unsigned long long acc[8];
#pragma unroll
        for (int m = 0; m < 8; m++) acc[m] = 0ull;

        if (homo) {
            const float* wb = ty[0] ? Wd : Wm;

            // Preload chunk 0 (x and W) into registers.
            ulonglong2 xa[8], xb[8];
#pragma unroll
            for (int m = 0; m < 8; m++) xa[m] = *(const ulonglong2*)&xs[nb + m][0];
            float u0 = __ldg(wb + 0 * F + feat);
            float u1 = __ldg(wb + 1 * F + feat);
            float u2 = __ldg(wb + 2 * F + feat);
            float u3 = __ldg(wb + 3 * F + feat);

#pragma unroll 1
            for (int k = 0; k < D; k += 8) {
                // --- half 1: consume chunk k (xa, u*), prefetch chunk k+4 ---
                unsigned long long w01 = pack2(u0, u1), w23 = pack2(u2, u3);
                float v0 = __ldg(wb + (k + 4) * F + feat);
                float v1 = __ldg(wb + (k + 5) * F + feat);
                float v2 = __ldg(wb + (k + 6) * F + feat);
                float v3 = __ldg(wb + (k + 7) * F + feat);
#pragma unroll
                for (int m = 0; m < 8; m++)
                    xb[m] = *(const ulonglong2*)&xs[nb + m][k + 4];
#pragma unroll
                for (int m = 0; m < 8; m++) {
                    fma2(acc[m], xa[m].x, w01);
                    fma2(acc[m], xa[m].y, w23);
                }

                // --- half 2: consume chunk k+4 (xb, v*), prefetch chunk k+8 ---
                unsigned long long v01 = pack2(v0, v1), v23 = pack2(v2, v3);
                if (k + 8 < D) {
                    u0 = __ldg(wb + (k + 8) * F + feat);
                    u1 = __ldg(wb + (k + 9) * F + feat);
                    u2 = __ldg(wb + (k + 10) * F + feat);
                    u3 = __ldg(wb + (k + 11) * F + feat);
#pragma unroll
                    for (int m = 0; m < 8; m++)
                        xa[m] = *(const ulonglong2*)&xs[nb + m][k + 8];
                }
#pragma unroll
                for (int m = 0; m < 8; m++) {
                    fma2(acc[m], xb[m].x, v01);
                    fma2(acc[m], xb[m].y, v23);
                }
            }
        } else {
            // Rare boundary block: per-node W, same even/odd summation order.
#pragma unroll 1
            for (int m = 0; m < 8; m++) {
                const float* wbm = ty[nb + m] ? Wd : Wm;
                for (int k = 0; k < D; k += 4) {
                    unsigned long long w01 = pack2(__ldg(wbm + (k + 0) * F + feat),
                                                   __ldg(wbm + (k + 1) * F + feat));
                    unsigned long long w23 = pack2(__ldg(wbm + (k + 2) * F + feat),
                                                   __ldg(wbm + (k + 3) * F + feat));
                    ulonglong2 x = *(const ulonglong2*)&xs[nb + m][k];
                    fma2(acc[m], x.x, w01);
                    fma2(acc[m], x.y, w23);
                }
            }
        }

#pragma unroll
        for (int m = 0; m < 8; m++) {
            int slot = slot_base + nb + m;
            if (slot < N) g_z[(long)ids[nb + m] * F + feat] = lo32(acc[m]) + hi32(acc[m]);
        }
    } else {
        int i = (bid - PB) * 128 + threadIdx.x;
        if (i < 2) g_pcnt[i] = 0;      // reset for next call
        int stride = SB_BLOCKS * 128;
        for (; i < E; i += stride) {
            int pos = atomicAdd(&g_cursor[dst[i]], 1);
            g_csr_src[pos] = src[i];
        }
    }
}

// L5: fused online-softmax aggregation + ELU (half-warp per dst node).
// 2-deep prefetch; __ldcg row gathers (L2-only — z is 12.8MB, keep L1 for idx).
__global__ void k_fused(float* __restrict__ out, int N, int E) {
    int hw = blockIdx.x * (blockDim.x >> 4) + (threadIdx.x >> 4);
    int lane = threadIdx.x & 15;
    unsigned mask = 0xFFFFu << (threadIdx.x & 0x10);
    if (hw >= N) return;
    int d = hw;

    int beg = g_start[d];
    int end = (d + 1 < N) ? g_start[d + 1] : E;

    if (beg == end) {
        ((float4*)(out + (long)d * F))[lane] = make_float4(0.f, 0.f, 0.f, 0.f);
        return;
    }

    float4 zd = __ldg(((const float4*)(g_z + (long)d * F)) + lane);

    float m = -INFINITY, s = 0.0f;
    float4 h = make_float4(0.f, 0.f, 0.f, 0.f);

    // 2-deep pipeline: idx 2-ahead, row 1-ahead
    int i0 = __ldg(g_csr_src + beg);
    float4 zs = __ldcg(((const float4*)(g_z + (long)i0 * F)) + lane);
    int i1 = (beg + 1 < end) ? __ldg(g_csr_src + beg + 1) : 0;

    for (int e = beg; e < end; e++) {
        float4 cur = zs;
        if (e + 1 < end)
            zs = __ldcg(((const float4*)(g_z + (long)i1 * F)) + lane);
        if (e + 2 < end)
            i1 = __ldg(g_csr_src + e + 2);

        float p = cur.x * zd.x + cur.y * zd.y + cur.z * zd.z + cur.w * zd.w;
        p += __shfl_xor_sync(mask, p, 1);
        p += __shfl_xor_sync(mask, p, 2);
        p += __shfl_xor_sync(mask, p, 4);
        p += __shfl_xor_sync(mask, p, 8);
        float ea = p > 0.0f ? p : 0.2f * p;          // leaky_relu
        if (ea <= m) {
            float w = __expf(ea - m);
            s += w;
            h.x = fmaf(w, cur.x, h.x);
            h.y = fmaf(w, cur.y, h.y);
            h.z = fmaf(w, cur.z, h.z);
            h.w = fmaf(w, cur.w, h.w);
        } else {
            float c = __expf(m - ea);                // first iter: exp(-inf)=0
            s = fmaf(s, c, 1.0f);
            h.x = fmaf(h.x, c, cur.x);
            h.y = fmaf(h.y, c, cur.y);
            h.z = fmaf(h.z, c, cur.z);
            h.w = fmaf(h.w, c, cur.w);
            m = ea;
        }
    }

    float inv = 1.0f / s;                            // s >= 1 (max term)
    float4 o;
    float x;
    x = h.x * inv; o.x = x > 0.0f ? x : expm1f(x);
    x = h.y * inv; o.y = x > 0.0f ? x : expm1f(x);
    x = h.z * inv; o.z = x > 0.0f ? x : expm1f(x);
    x = h.w * inv; o.w = x > 0.0f ? x : expm1f(x);
    ((float4*)(out + (long)d * F))[lane] = o;
}

extern "C" void kernel_launch(void* const* d_in, const int* in_sizes, int n_in,
                              void* d_out, int out_size) {
    const float* d_sim = (const float*)d_in[0];
    const float* m_sim = (const float*)d_in[1];
    const float* Wd    = (const float*)d_in[2];
    const float* Wm    = (const float*)d_in[3];
    const int*   ntype = (const int*)d_in[4];
    const int*   src   = (const int*)d_in[5];
    const int*   dst   = (const int*)d_in[6];
    float* out = (float*)d_out;

    int N = in_sizes[4];
    int E = in_sizes[5];
    int NB = (N + SCAN_BS - 1) / SCAN_BS;
    int PB = (N + 15) / 16;

    k_pre<<<(max(N, E) + 255) / 256, 256>>>(ntype, dst, N, E);
    k_scan_blocks<<<NB, SCAN_BS>>>(N);
    k_addoff<<<(N + 255) / 256, 256>>>(N, NB);
    k_m2<<<PB + SB_BLOCKS, 128>>>(d_sim, m_sim, Wd, Wm, ntype, src, dst, N, E, PB);
    {
        int hw_per_block = 256 / 16;
        int blocks = (N + hw_per_block - 1) / hw_per_block;
        k_fused<<<blocks, 256>>>(out, N, E);
    }
}